// round 11
// baseline (speedup 1.0000x reference)
#include <cuda_runtime.h>
#include <cuda_bf16.h>
#include <cstdint>

#define BSZ    256
#define FEAT   128
#define KP1    4097
#define PAD    4100
#define NDATA  500000
#define SDIM   1024
#define TDIM   2048
#define MEMELEMS 64000000
#define TOTAL  (BSZ * KP1)        // 1,048,832
#define EPSF   1e-7f
#define MPN    (4096.0f / 500000.0f)
#define KSPLIT 8
#define FULLM  0xffffffffu
#define CAP    24
#define MEGA_CTAS 148
#define MEGA_THR  1024
#define NWARPS   (MEGA_CTAS * 32)  // 4736
#define CHUNK    106               // 4736*106 = 502,016 >= NDATA

__device__ float g_es[BSZ * FEAT];
__device__ float g_et[BSZ * FEAT];
__device__ float g_part_s[KSPLIT * BSZ * FEAT];
__device__ float g_part_t[KSPLIT * BSZ * FEAT];
__device__ float g_out_s[BSZ * PAD];
__device__ float g_out_t[BSZ * PAD];
__device__ float g_sums[3];          // zero-init; self-cleaned each replay
__device__ int   g_ticket;
__device__ int   g_rtcnt[128];       // zero-init; self-resetting
__device__ int   g_cnt[NDATA];       // zero-init; cleaned in mega P3
__device__ int   g_tasklist[NDATA * CAP];
__device__ int   g_bar_cnt;          // zero-init; self-resetting
__device__ volatile int g_bar_gen;   // monotonic across replays

// ---------------------------------------------------------------- grid barrier (all 148 CTAs resident)
__device__ __forceinline__ void grid_sync() {
    __threadfence();
    __syncthreads();
    if (threadIdx.x == 0) {
        const int gen = g_bar_gen;
        if (atomicAdd(&g_bar_cnt, 1) == MEGA_CTAS - 1) {
            g_bar_cnt = 0;
            __threadfence();
            g_bar_gen = gen + 1;
        } else {
            while (g_bar_gen == gen) { }
        }
        __threadfence();
    }
    __syncthreads();
}

// ---------------------------------------------------------------- L1: embed partial + scatter + ticket-norm
// bid<1024: split-K embed (last ksplit block per rowtile normalizes). bid>=1024: scatter.
__global__ __launch_bounds__(128) void embed_scatter(const float* __restrict__ f_s,
                                                     const float* __restrict__ f_t,
                                                     const float* __restrict__ W_s,
                                                     const float* __restrict__ W_t,
                                                     const float* __restrict__ b_s,
                                                     const float* __restrict__ b_t,
                                                     const int* __restrict__ cidx) {
    const int bid = blockIdx.x;
    const int t = threadIdx.x;
    if (bid >= 1024) {
        const int tid = (bid - 1024) * 128 + t;
        #pragma unroll 1
        for (int i = tid; i < TOTAL; i += 1024 * 128) {
            const int row = __ldg(cidx + i);
            const int pos = atomicAdd(&g_cnt[row], 1);
            if (pos < CAP)
                g_tasklist[(size_t)row * CAP + pos] = i;
        }
        return;
    }
    __shared__ float fsh[4 * 256];
    __shared__ float sh[4];
    __shared__ int sh_last;
    const bool is_t = bid >= 512;
    const int id = is_t ? bid - 512 : bid;
    const int rt = id >> 3;
    const int ks = id & 7;
    const int Kd = is_t ? TDIM : SDIM;
    const int kchunk = Kd / KSPLIT;
    const int k0 = ks * kchunk;
    const float* f = is_t ? f_t : f_s;
    const float* W = is_t ? W_t : W_s;
    float* part = is_t ? g_part_t : g_part_s;
    const int rows0 = rt * 4;

    #pragma unroll
    for (int r = 0; r < 4; ++r)
        for (int k = t; k < kchunk; k += 128)
            fsh[r * 256 + k] = f[(rows0 + r) * Kd + k0 + k];
    __syncthreads();

    float a0 = 0.f, a1 = 0.f, a2 = 0.f, a3 = 0.f;
    const float* Wp = W + (size_t)k0 * FEAT + t;
    #pragma unroll 8
    for (int k = 0; k < kchunk; ++k) {
        float w = Wp[(size_t)k * FEAT];
        a0 += fsh[k] * w;
        a1 += fsh[256 + k] * w;
        a2 += fsh[512 + k] * w;
        a3 += fsh[768 + k] * w;
    }
    part[(ks * BSZ + rows0 + 0) * FEAT + t] = a0;
    part[(ks * BSZ + rows0 + 1) * FEAT + t] = a1;
    part[(ks * BSZ + rows0 + 2) * FEAT + t] = a2;
    part[(ks * BSZ + rows0 + 3) * FEAT + t] = a3;

    __threadfence();
    __syncthreads();
    const int tcx = (is_t ? 64 : 0) + rt;
    if (t == 0) sh_last = (atomicAdd(&g_rtcnt[tcx], 1) == KSPLIT - 1);
    __syncthreads();
    if (!sh_last) return;
    __threadfence();

    const float* bias = is_t ? b_t : b_s;
    float* out = is_t ? g_et : g_es;
    const int lane = t & 31, w_ = t >> 5;
    #pragma unroll
    for (int r = 0; r < 4; ++r) {
        float v = bias[t];
        #pragma unroll
        for (int kk = 0; kk < KSPLIT; ++kk)
            v += part[(kk * BSZ + rows0 + r) * FEAT + t];
        float sq = v * v;
        #pragma unroll
        for (int o = 16; o; o >>= 1) sq += __shfl_xor_sync(FULLM, sq, o);
        if (lane == 0) sh[w_] = sq;
        __syncthreads();
        float tot = sh[0] + sh[1] + sh[2] + sh[3];
        __syncthreads();
        out[(rows0 + r) * FEAT + t] = v / sqrtf(tot);
    }
    if (t == 0) g_rtcnt[tcx] = 0;
}

// ---------------------------------------------------------------- L2: MEGA (sweep + barrier + loss/update)
__global__ __launch_bounds__(MEGA_THR, 1) void mega_kernel(const float* __restrict__ m1,
                                                           const float* __restrict__ m2,
                                                           const int* __restrict__ idx,
                                                           float* __restrict__ out) {
    extern __shared__ char sm[];
    __nv_bfloat16* esb = (__nv_bfloat16*)sm;              // 64 KB
    __nv_bfloat16* etb = (__nv_bfloat16*)(sm + 65536);    // 64 KB
    __shared__ float shT[32], shS[32];

    const int t = threadIdx.x;
    for (int i = t; i < BSZ * FEAT; i += MEGA_THR) {
        esb[i] = __float2bfloat16(g_es[i]);
        etb[i] = __float2bfloat16(g_et[i]);
    }
    __syncthreads();

    const int lane = t & 31;
    const int w = t >> 5;
    const int gw = blockIdx.x * 32 + w;
    const int r0 = gw * CHUNK;
    const int rend = min(r0 + CHUNK, NDATA);

    float sumT = 0.f, sumS = 0.f;

    // ======== Phase 1: single-pass row sweep (copy + NCE from one load) ========
    if (r0 < rend) {
        float4* o1b = (float4*)out;
        float4* o2b = (float4*)(out + MEMELEMS);

        float carry1 = 0.f, carry2 = 0.f;
        if (r0 > 0 && lane == 0) {
            carry1 = __ldg(m1 + (size_t)r0 * FEAT - 1);
            carry2 = __ldg(m2 + (size_t)r0 * FEAT - 1);
        }

        float4 A = __ldg((const float4*)m1 + (size_t)r0 * 32 + lane);
        float4 C = __ldg((const float4*)m2 + (size_t)r0 * 32 + lane);
        int cnt = __ldg(&g_cnt[r0]);

        #pragma unroll 1
        for (int r = r0; r < rend; ++r) {
            float4 A2, C2; int cnt2 = 0;
            if (r + 1 < rend) {
                A2 = __ldg((const float4*)m1 + (size_t)(r + 1) * 32 + lane);
                C2 = __ldg((const float4*)m2 + (size_t)(r + 1) * 32 + lane);
                cnt2 = __ldg(&g_cnt[r + 1]);
            }

            const int c = min(cnt, CAP);
            if (c > 0) {
                int rec = 0;
                if (lane < c) rec = __ldg(&g_tasklist[(size_t)r * CAP + lane]);
                #pragma unroll 1
                for (int tt = 0; tt < c; tt += 2) {
                    const bool has2 = (tt + 1 < c);
                    const int i0 = __shfl_sync(FULLM, rec, tt);
                    const int i1 = __shfl_sync(FULLM, rec, has2 ? tt + 1 : tt);
                    const int b0 = i0 / KP1, k0 = i0 - b0 * KP1;
                    const int b1 = i1 / KP1, k1 = i1 - b1 * KP1;
                    const __nv_bfloat162* ept0 = (const __nv_bfloat162*)(etb + b0 * FEAT) + lane * 2;
                    const __nv_bfloat162* eps0 = (const __nv_bfloat162*)(esb + b0 * FEAT) + lane * 2;
                    const __nv_bfloat162* ept1 = (const __nv_bfloat162*)(etb + b1 * FEAT) + lane * 2;
                    const __nv_bfloat162* eps1 = (const __nv_bfloat162*)(esb + b1 * FEAT) + lane * 2;
                    const float2 ta0 = __bfloat1622float2(ept0[0]);
                    const float2 ta1 = __bfloat1622float2(ept0[1]);
                    const float2 sa0 = __bfloat1622float2(eps0[0]);
                    const float2 sa1 = __bfloat1622float2(eps0[1]);
                    const float2 tb0 = __bfloat1622float2(ept1[0]);
                    const float2 tb1 = __bfloat1622float2(ept1[1]);
                    const float2 sb0 = __bfloat1622float2(eps1[0]);
                    const float2 sb1 = __bfloat1622float2(eps1[1]);
                    float dt0 = A.x * ta0.x + A.y * ta0.y + A.z * ta1.x + A.w * ta1.y;
                    float ds0 = C.x * sa0.x + C.y * sa0.y + C.z * sa1.x + C.w * sa1.y;
                    float dt1 = A.x * tb0.x + A.y * tb0.y + A.z * tb1.x + A.w * tb1.y;
                    float ds1 = C.x * sb0.x + C.y * sb0.y + C.z * sb1.x + C.w * sb1.y;
                    #pragma unroll
                    for (int o = 16; o; o >>= 1) {
                        dt0 += __shfl_xor_sync(FULLM, dt0, o);
                        ds0 += __shfl_xor_sync(FULLM, ds0, o);
                        dt1 += __shfl_xor_sync(FULLM, dt1, o);
                        ds1 += __shfl_xor_sync(FULLM, ds1, o);
                    }
                    if (lane == 0) {
                        const float ot0 = __expf(dt0 * (1.0f / 0.07f));
                        const float os0 = __expf(ds0 * (1.0f / 0.07f));
                        g_out_t[b0 * PAD + k0] = ot0;
                        g_out_s[b0 * PAD + k0] = os0;
                        sumT += ot0; sumS += os0;
                        if (has2) {
                            const float ot1 = __expf(dt1 * (1.0f / 0.07f));
                            const float os1 = __expf(ds1 * (1.0f / 0.07f));
                            g_out_t[b1 * PAD + k1] = ot1;
                            g_out_s[b1 * PAD + k1] = os1;
                            sumT += ot1; sumS += os1;
                        }
                    }
                }
            }

            // copy-out (shifted +1): aligned float4 stores via shfl carry
            float p1 = __shfl_up_sync(FULLM, A.w, 1);
            float p2 = __shfl_up_sync(FULLM, C.w, 1);
            if (lane == 0) { p1 = carry1; p2 = carry2; }
            const int ci = r * 32 + lane;
            if (r == 0 && lane == 0) {
                out[1] = A.x; out[2] = A.y; out[3] = A.z;
                out[MEMELEMS + 1] = C.x; out[MEMELEMS + 2] = C.y; out[MEMELEMS + 3] = C.z;
            } else {
                o1b[ci] = make_float4(p1, A.x, A.y, A.z);
                o2b[ci] = make_float4(p2, C.x, C.y, C.z);
            }
            if (r == NDATA - 1 && lane == 31) {
                out[MEMELEMS] = A.w;
                out[(size_t)2 * MEMELEMS] = C.w;
            }
            carry1 = __shfl_sync(FULLM, A.w, 31);
            carry2 = __shfl_sync(FULLM, C.w, 31);
            A = A2; C = C2; cnt = cnt2;
        }
    }

    if (lane == 0) { shT[w] = sumT; shS[w] = sumS; }
    __syncthreads();
    if (t == 0) {
        float aT = 0.f, aS = 0.f;
        #pragma unroll
        for (int i = 0; i < 32; ++i) { aT += shT[i]; aS += shS[i]; }
        atomicAdd(&g_sums[0], aT);
        atomicAdd(&g_sums[1], aS);
    }

    // ======== barrier: all sums + copy + g_out visible ========
    grid_sync();

    // ======== Phase 2: loss (all threads) + update (first 256 warps) + cleanup ========
    const int gt = blockIdx.x * MEGA_THR + t;
    const int T = MEGA_CTAS * MEGA_THR;

    // update: one warp per batch row
    if (gw < BSZ) {
        const int b = gw;
        const int row = __ldg(idx + b);
        float* o1 = out + 1;
        float* o2 = out + 1 + MEMELEMS;
        const float4 mv1 = __ldg((const float4*)m1 + (size_t)row * 32 + lane);
        const float4 mv2 = __ldg((const float4*)m2 + (size_t)row * 32 + lane);
        const float4 e1 = *((const float4*)(g_es + b * FEAT) + lane);
        const float4 e2 = *((const float4*)(g_et + b * FEAT) + lane);
        float v1[4] = {0.5f * (mv1.x + e1.x), 0.5f * (mv1.y + e1.y),
                       0.5f * (mv1.z + e1.z), 0.5f * (mv1.w + e1.w)};
        float v2[4] = {0.5f * (mv2.x + e2.x), 0.5f * (mv2.y + e2.y),
                       0.5f * (mv2.z + e2.z), 0.5f * (mv2.w + e2.w)};
        float s1 = v1[0]*v1[0] + v1[1]*v1[1] + v1[2]*v1[2] + v1[3]*v1[3];
        float s2 = v2[0]*v2[0] + v2[1]*v2[1] + v2[2]*v2[2] + v2[3]*v2[3];
        #pragma unroll
        for (int o = 16; o; o >>= 1) {
            s1 += __shfl_xor_sync(FULLM, s1, o);
            s2 += __shfl_xor_sync(FULLM, s2, o);
        }
        const float in1 = rsqrtf(s1), in2 = rsqrtf(s2);
        const size_t off = (size_t)row * FEAT + lane * 4;
        #pragma unroll
        for (int j = 0; j < 4; ++j) {
            o1[off + j] = v1[j] * in1;
            o2[off + j] = v2[j] * in2;
        }
    }

    // loss: grid-strided over (b, k-group) items
    {
        const float invZt = (float)TOTAL / ((float)NDATA * g_sums[0]);
        const float invZs = (float)TOTAL / ((float)NDATA * g_sums[1]);
        float acc = 0.f;
        #pragma unroll 1
        for (int it = gt; it < BSZ * 1025; it += T) {
            const int b = it / 1025;
            const int k = (it - b * 1025) * 4;
            float4 vs = *((const float4*)(g_out_s + b * PAD + k));
            float4 vt = *((const float4*)(g_out_t + b * PAD + k));
            float xs[4] = {vs.x, vs.y, vs.z, vs.w};
            float xt[4] = {vt.x, vt.y, vt.z, vt.w};
            #pragma unroll
            for (int c = 0; c < 4; ++c) {
                if (k + c < KP1) {
                    float xS = xs[c] * invZs;
                    float xT = xt[c] * invZt;
                    if (k + c == 0) {
                        acc += logf(xS / (xS + MPN + EPSF)) + logf(xT / (xT + MPN + EPSF));
                    } else {
                        acc -= logf(1.0f + (xS + EPSF) * (1.0f / MPN));
                        acc -= logf(1.0f + (xT + EPSF) * (1.0f / MPN));
                    }
                }
            }
        }
        #pragma unroll
        for (int o = 16; o; o >>= 1) acc += __shfl_xor_sync(FULLM, acc, o);
        if (lane == 0) shT[w] = acc;
    }

    // cleanup g_cnt for next replay
    #pragma unroll 1
    for (int z = gt; z < NDATA; z += T) g_cnt[z] = 0;

    __syncthreads();
    if (t == 0) {
        float tot = 0.f;
        #pragma unroll
        for (int i = 0; i < 32; ++i) tot += shT[i];
        atomicAdd(&g_sums[2], tot);
        __threadfence();
        const int tk = atomicAdd(&g_ticket, 1);
        if (tk == MEGA_CTAS - 1) {
            out[0] = -g_sums[2] / (float)BSZ;
            g_sums[0] = 0.f; g_sums[1] = 0.f; g_sums[2] = 0.f;
            g_ticket = 0;
        }
    }
}

// ---------------------------------------------------------------- launch
extern "C" void kernel_launch(void* const* d_in, const int* in_sizes, int n_in,
                              void* d_out, int out_size) {
    const float* f_s  = (const float*)d_in[0];
    const float* f_t  = (const float*)d_in[1];
    const int*   idx  = (const int*)  d_in[2];
    const int*   cidx = (const int*)  d_in[3];
    const float* W_s  = (const float*)d_in[4];
    const float* b_s  = (const float*)d_in[5];
    const float* W_t  = (const float*)d_in[6];
    const float* b_t  = (const float*)d_in[7];
    const float* m1   = (const float*)d_in[8];
    const float* m2   = (const float*)d_in[9];
    float* out = (float*)d_out;

    static int smem_set = 0;
    const int MEGA_SMEM = 131072;
    if (!smem_set) {
        cudaFuncSetAttribute(mega_kernel, cudaFuncAttributeMaxDynamicSharedMemorySize, MEGA_SMEM);
        smem_set = 1;
    }

    embed_scatter<<<2048, 128>>>(f_s, f_t, W_s, W_t, b_s, b_t, cidx);
    mega_kernel<<<MEGA_CTAS, MEGA_THR, MEGA_SMEM>>>(m1, m2, idx, out);
}

// round 12
// speedup vs baseline: 1.0877x; 1.0877x over previous
#include <cuda_runtime.h>
#include <cuda_bf16.h>
#include <cstdint>

#define BSZ    256
#define FEAT   128
#define KP1    4097
#define PAD    4100
#define NDATA  500000
#define SDIM   1024
#define TDIM   2048
#define MEMELEMS 64000000
#define TOTAL  (BSZ * KP1)        // 1,048,832
#define EPSF   1e-7f
#define MPN    (4096.0f / 500000.0f)
#define KSPLIT 8
#define FULLM  0xffffffffu
#define CAP    24
#define MEGA_CTAS 148
#define MEGA_THR  1024
#define NWARPS   (MEGA_CTAS * 32)  // 4736
#define CHUNK    106               // 4736*106 = 502,016 >= NDATA

__device__ float g_es[BSZ * FEAT];
__device__ float g_et[BSZ * FEAT];
__device__ float g_part_s[KSPLIT * BSZ * FEAT];
__device__ float g_part_t[KSPLIT * BSZ * FEAT];
__device__ float g_out_s[BSZ * PAD];
__device__ float g_out_t[BSZ * PAD];
__device__ float g_sums[3];          // zero-init; self-cleaned each replay
__device__ int   g_ticket;
__device__ int   g_rtcnt[128];       // zero-init; self-resetting
__device__ int   g_cnt[NDATA];       // zero-init; cleaned in mega P2
__device__ int   g_tasklist[NDATA * CAP];   // packed rec = (b<<13)|k
__device__ int   g_bar_cnt;          // zero-init; self-resetting
__device__ volatile int g_bar_gen;   // monotonic across replays

// ---------------------------------------------------------------- grid barrier (all 148 CTAs resident)
__device__ __forceinline__ void grid_sync() {
    __threadfence();
    __syncthreads();
    if (threadIdx.x == 0) {
        const int gen = g_bar_gen;
        if (atomicAdd(&g_bar_cnt, 1) == MEGA_CTAS - 1) {
            g_bar_cnt = 0;
            __threadfence();
            g_bar_gen = gen + 1;
        } else {
            while (g_bar_gen == gen) { }
        }
        __threadfence();
    }
    __syncthreads();
}

// ---------------------------------------------------------------- L1: embed partial + scatter + ticket-norm
__global__ __launch_bounds__(128) void embed_scatter(const float* __restrict__ f_s,
                                                     const float* __restrict__ f_t,
                                                     const float* __restrict__ W_s,
                                                     const float* __restrict__ W_t,
                                                     const float* __restrict__ b_s,
                                                     const float* __restrict__ b_t,
                                                     const int* __restrict__ cidx) {
    const int bid = blockIdx.x;
    const int t = threadIdx.x;
    if (bid >= 1024) {
        const int tid = (bid - 1024) * 128 + t;
        #pragma unroll 1
        for (int i = tid; i < TOTAL; i += 1024 * 128) {
            const int row = __ldg(cidx + i);
            const int b = i / KP1;
            const int k = i - b * KP1;
            const int pos = atomicAdd(&g_cnt[row], 1);
            if (pos < CAP)
                g_tasklist[(size_t)row * CAP + pos] = (b << 13) | k;
        }
        return;
    }
    __shared__ float fsh[4 * 256];
    __shared__ float sh[4];
    __shared__ int sh_last;
    const bool is_t = bid >= 512;
    const int id = is_t ? bid - 512 : bid;
    const int rt = id >> 3;
    const int ks = id & 7;
    const int Kd = is_t ? TDIM : SDIM;
    const int kchunk = Kd / KSPLIT;
    const int k0 = ks * kchunk;
    const float* f = is_t ? f_t : f_s;
    const float* W = is_t ? W_t : W_s;
    float* part = is_t ? g_part_t : g_part_s;
    const int rows0 = rt * 4;

    #pragma unroll
    for (int r = 0; r < 4; ++r)
        for (int k = t; k < kchunk; k += 128)
            fsh[r * 256 + k] = f[(rows0 + r) * Kd + k0 + k];
    __syncthreads();

    float a0 = 0.f, a1 = 0.f, a2 = 0.f, a3 = 0.f;
    const float* Wp = W + (size_t)k0 * FEAT + t;
    #pragma unroll 8
    for (int k = 0; k < kchunk; ++k) {
        float w = Wp[(size_t)k * FEAT];
        a0 += fsh[k] * w;
        a1 += fsh[256 + k] * w;
        a2 += fsh[512 + k] * w;
        a3 += fsh[768 + k] * w;
    }
    part[(ks * BSZ + rows0 + 0) * FEAT + t] = a0;
    part[(ks * BSZ + rows0 + 1) * FEAT + t] = a1;
    part[(ks * BSZ + rows0 + 2) * FEAT + t] = a2;
    part[(ks * BSZ + rows0 + 3) * FEAT + t] = a3;

    __threadfence();
    __syncthreads();
    const int tcx = (is_t ? 64 : 0) + rt;
    if (t == 0) sh_last = (atomicAdd(&g_rtcnt[tcx], 1) == KSPLIT - 1);
    __syncthreads();
    if (!sh_last) return;
    __threadfence();

    const float* bias = is_t ? b_t : b_s;
    float* out = is_t ? g_et : g_es;
    const int lane = t & 31, w_ = t >> 5;
    #pragma unroll
    for (int r = 0; r < 4; ++r) {
        float v = bias[t];
        #pragma unroll
        for (int kk = 0; kk < KSPLIT; ++kk)
            v += part[(kk * BSZ + rows0 + r) * FEAT + t];
        float sq = v * v;
        #pragma unroll
        for (int o = 16; o; o >>= 1) sq += __shfl_xor_sync(FULLM, sq, o);
        if (lane == 0) sh[w_] = sq;
        __syncthreads();
        float tot = sh[0] + sh[1] + sh[2] + sh[3];
        __syncthreads();
        out[(rows0 + r) * FEAT + t] = v / sqrtf(tot);
    }
    if (t == 0) g_rtcnt[tcx] = 0;
}

// ---------------------------------------------------------------- L2: MEGA
// smem: interleaved bf16 embeddings eint[b*32+lane] = {es[4], et[4]} (128 KB)
__global__ __launch_bounds__(MEGA_THR, 1) void mega_kernel(const float* __restrict__ m1,
                                                           const float* __restrict__ m2,
                                                           const int* __restrict__ idx,
                                                           float* __restrict__ out) {
    extern __shared__ char sm[];
    uint4* eint = (uint4*)sm;                 // 128 KB
    __shared__ float shT[32], shS[32];

    const int t = threadIdx.x;
    for (int i = t; i < BSZ * 32; i += MEGA_THR) {
        const int b = i >> 5, l = i & 31;
        const float4 e1 = *((const float4*)(g_es + b * FEAT) + l);
        const float4 e2 = *((const float4*)(g_et + b * FEAT) + l);
        uint4 e;
        __nv_bfloat162 v;
        v = __floats2bfloat162_rn(e1.x, e1.y); e.x = *(unsigned*)&v;
        v = __floats2bfloat162_rn(e1.z, e1.w); e.y = *(unsigned*)&v;
        v = __floats2bfloat162_rn(e2.x, e2.y); e.z = *(unsigned*)&v;
        v = __floats2bfloat162_rn(e2.z, e2.w); e.w = *(unsigned*)&v;
        eint[i] = e;
    }
    __syncthreads();

    const int lane = t & 31;
    const int w = t >> 5;
    const int gw = blockIdx.x * 32 + w;
    const int r0 = gw * CHUNK;
    const int rend = min(r0 + CHUNK, NDATA);

    float sumT = 0.f, sumS = 0.f;

    // ======== Phase 1: single-pass row sweep ========
    if (r0 < rend) {
        float4* o1b = (float4*)out;
        float4* o2b = (float4*)(out + MEMELEMS);

        float carry1 = 0.f, carry2 = 0.f;
        if (r0 > 0 && lane == 0) {
            carry1 = __ldg(m1 + (size_t)r0 * FEAT - 1);
            carry2 = __ldg(m2 + (size_t)r0 * FEAT - 1);
        }

        // prefetch first row (incl. its task records, unconditional lane<CAP)
        float4 A = __ldg((const float4*)m1 + (size_t)r0 * 32 + lane);
        float4 C = __ldg((const float4*)m2 + (size_t)r0 * 32 + lane);
        int cnt = __ldg(&g_cnt[r0]);
        int rec = (lane < CAP) ? __ldg(&g_tasklist[(size_t)r0 * CAP + lane]) : 0;

        #pragma unroll 1
        for (int r = r0; r < rend; ++r) {
            float4 A2 = make_float4(0.f,0.f,0.f,0.f), C2 = A2;
            int cnt2 = 0, rec2 = 0;
            if (r + 1 < rend) {
                A2 = __ldg((const float4*)m1 + (size_t)(r + 1) * 32 + lane);
                C2 = __ldg((const float4*)m2 + (size_t)(r + 1) * 32 + lane);
                cnt2 = __ldg(&g_cnt[r + 1]);
                if (lane < CAP) rec2 = __ldg(&g_tasklist[(size_t)(r + 1) * CAP + lane]);
            }

            // ---- NCE dots (pairs; one LDS.128 per task; packed recs, no div)
            const int c = min(cnt, CAP);
            #pragma unroll 1
            for (int tt = 0; tt < c; tt += 2) {
                const bool has2 = (tt + 1 < c);
                const int rA = __shfl_sync(FULLM, rec, tt);
                const int rB = __shfl_sync(FULLM, rec, has2 ? tt + 1 : tt);
                const int bA = rA >> 13, kA = rA & 8191;
                const int bB = rB >> 13, kB = rB & 8191;
                const uint4 eA = eint[(bA << 5) + lane];
                const uint4 eB = eint[(bB << 5) + lane];
                const float2 sA0 = __bfloat1622float2(*(const __nv_bfloat162*)&eA.x);
                const float2 sA1 = __bfloat1622float2(*(const __nv_bfloat162*)&eA.y);
                const float2 tA0 = __bfloat1622float2(*(const __nv_bfloat162*)&eA.z);
                const float2 tA1 = __bfloat1622float2(*(const __nv_bfloat162*)&eA.w);
                const float2 sB0 = __bfloat1622float2(*(const __nv_bfloat162*)&eB.x);
                const float2 sB1 = __bfloat1622float2(*(const __nv_bfloat162*)&eB.y);
                const float2 tB0 = __bfloat1622float2(*(const __nv_bfloat162*)&eB.z);
                const float2 tB1 = __bfloat1622float2(*(const __nv_bfloat162*)&eB.w);
                float dtA = A.x * tA0.x + A.y * tA0.y + A.z * tA1.x + A.w * tA1.y;
                float dsA = C.x * sA0.x + C.y * sA0.y + C.z * sA1.x + C.w * sA1.y;
                float dtB = A.x * tB0.x + A.y * tB0.y + A.z * tB1.x + A.w * tB1.y;
                float dsB = C.x * sB0.x + C.y * sB0.y + C.z * sB1.x + C.w * sB1.y;
                #pragma unroll
                for (int o = 16; o; o >>= 1) {
                    dtA += __shfl_xor_sync(FULLM, dtA, o);
                    dsA += __shfl_xor_sync(FULLM, dsA, o);
                    dtB += __shfl_xor_sync(FULLM, dtB, o);
                    dsB += __shfl_xor_sync(FULLM, dsB, o);
                }
                if (lane == 0) {
                    const float otA = __expf(dtA * (1.0f / 0.07f));
                    const float osA = __expf(dsA * (1.0f / 0.07f));
                    g_out_t[bA * PAD + kA] = otA;
                    g_out_s[bA * PAD + kA] = osA;
                    sumT += otA; sumS += osA;
                    if (has2) {
                        const float otB = __expf(dtB * (1.0f / 0.07f));
                        const float osB = __expf(dsB * (1.0f / 0.07f));
                        g_out_t[bB * PAD + kB] = otB;
                        g_out_s[bB * PAD + kB] = osB;
                        sumT += otB; sumS += osB;
                    }
                }
            }

            // ---- copy-out (shifted +1): aligned float4 stores via shfl carry
            float p1 = __shfl_up_sync(FULLM, A.w, 1);
            float p2 = __shfl_up_sync(FULLM, C.w, 1);
            if (lane == 0) { p1 = carry1; p2 = carry2; }
            const int ci = r * 32 + lane;
            if (r == 0 && lane == 0) {
                out[1] = A.x; out[2] = A.y; out[3] = A.z;
                out[MEMELEMS + 1] = C.x; out[MEMELEMS + 2] = C.y; out[MEMELEMS + 3] = C.z;
            } else {
                o1b[ci] = make_float4(p1, A.x, A.y, A.z);
                o2b[ci] = make_float4(p2, C.x, C.y, C.z);
            }
            if (r == NDATA - 1 && lane == 31) {
                out[MEMELEMS] = A.w;
                out[(size_t)2 * MEMELEMS] = C.w;
            }
            carry1 = __shfl_sync(FULLM, A.w, 31);
            carry2 = __shfl_sync(FULLM, C.w, 31);
            A = A2; C = C2; cnt = cnt2; rec = rec2;
        }
    }

    if (lane == 0) { shT[w] = sumT; shS[w] = sumS; }
    __syncthreads();
    if (t == 0) {
        float aT = 0.f, aS = 0.f;
        #pragma unroll
        for (int i = 0; i < 32; ++i) { aT += shT[i]; aS += shS[i]; }
        atomicAdd(&g_sums[0], aT);
        atomicAdd(&g_sums[1], aS);
    }

    // ======== barrier ========
    grid_sync();

    // ======== Phase 2: loss + update + cleanup ========
    const int gt = blockIdx.x * MEGA_THR + t;
    const int T = MEGA_CTAS * MEGA_THR;

    if (gw < BSZ) {
        const int b = gw;
        const int row = __ldg(idx + b);
        float* o1 = out + 1;
        float* o2 = out + 1 + MEMELEMS;
        const float4 mv1 = __ldg((const float4*)m1 + (size_t)row * 32 + lane);
        const float4 mv2 = __ldg((const float4*)m2 + (size_t)row * 32 + lane);
        const float4 e1 = *((const float4*)(g_es + b * FEAT) + lane);
        const float4 e2 = *((const float4*)(g_et + b * FEAT) + lane);
        float v1[4] = {0.5f * (mv1.x + e1.x), 0.5f * (mv1.y + e1.y),
                       0.5f * (mv1.z + e1.z), 0.5f * (mv1.w + e1.w)};
        float v2[4] = {0.5f * (mv2.x + e2.x), 0.5f * (mv2.y + e2.y),
                       0.5f * (mv2.z + e2.z), 0.5f * (mv2.w + e2.w)};
        float s1 = v1[0]*v1[0] + v1[1]*v1[1] + v1[2]*v1[2] + v1[3]*v1[3];
        float s2 = v2[0]*v2[0] + v2[1]*v2[1] + v2[2]*v2[2] + v2[3]*v2[3];
        #pragma unroll
        for (int o = 16; o; o >>= 1) {
            s1 += __shfl_xor_sync(FULLM, s1, o);
            s2 += __shfl_xor_sync(FULLM, s2, o);
        }
        const float in1 = rsqrtf(s1), in2 = rsqrtf(s2);
        const size_t off = (size_t)row * FEAT + lane * 4;
        #pragma unroll
        for (int j = 0; j < 4; ++j) {
            o1[off + j] = v1[j] * in1;
            o2[off + j] = v2[j] * in2;
        }
    }

    {
        const float invZt = (float)TOTAL / ((float)NDATA * g_sums[0]);
        const float invZs = (float)TOTAL / ((float)NDATA * g_sums[1]);
        float acc = 0.f;
        #pragma unroll 1
        for (int it = gt; it < BSZ * 1025; it += T) {
            const int b = it / 1025;
            const int k = (it - b * 1025) * 4;
            float4 vs = *((const float4*)(g_out_s + b * PAD + k));
            float4 vt = *((const float4*)(g_out_t + b * PAD + k));
            float xs[4] = {vs.x, vs.y, vs.z, vs.w};
            float xt[4] = {vt.x, vt.y, vt.z, vt.w};
            #pragma unroll
            for (int c = 0; c < 4; ++c) {
                if (k + c < KP1) {
                    float xS = xs[c] * invZs;
                    float xT = xt[c] * invZt;
                    if (k + c == 0) {
                        acc += logf(xS / (xS + MPN + EPSF)) + logf(xT / (xT + MPN + EPSF));
                    } else {
                        acc -= logf(1.0f + (xS + EPSF) * (1.0f / MPN));
                        acc -= logf(1.0f + (xT + EPSF) * (1.0f / MPN));
                    }
                }
            }
        }
        #pragma unroll
        for (int o = 16; o; o >>= 1) acc += __shfl_xor_sync(FULLM, acc, o);
        if (lane == 0) shT[w] = acc;
    }

    #pragma unroll 1
    for (int z = gt; z < NDATA; z += T) g_cnt[z] = 0;

    __syncthreads();
    if (t == 0) {
        float tot = 0.f;
        #pragma unroll
        for (int i = 0; i < 32; ++i) tot += shT[i];
        atomicAdd(&g_sums[2], tot);
        __threadfence();
        const int tk = atomicAdd(&g_ticket, 1);
        if (tk == MEGA_CTAS - 1) {
            out[0] = -g_sums[2] / (float)BSZ;
            g_sums[0] = 0.f; g_sums[1] = 0.f; g_sums[2] = 0.f;
            g_ticket = 0;
        }
    }
}

// ---------------------------------------------------------------- launch
extern "C" void kernel_launch(void* const* d_in, const int* in_sizes, int n_in,
                              void* d_out, int out_size) {
    const float* f_s  = (const float*)d_in[0];
    const float* f_t  = (const float*)d_in[1];
    const int*   idx  = (const int*)  d_in[2];
    const int*   cidx = (const int*)  d_in[3];
    const float* W_s  = (const float*)d_in[4];
    const float* b_s  = (const float*)d_in[5];
    const float* W_t  = (const float*)d_in[6];
    const float* b_t  = (const float*)d_in[7];
    const float* m1   = (const float*)d_in[8];
    const float* m2   = (const float*)d_in[9];
    float* out = (float*)d_out;

    static int smem_set = 0;
    const int MEGA_SMEM = 131072;
    if (!smem_set) {
        cudaFuncSetAttribute(mega_kernel, cudaFuncAttributeMaxDynamicSharedMemorySize, MEGA_SMEM);
        smem_set = 1;
    }

    embed_scatter<<<2048, 128>>>(f_s, f_t, W_s, W_t, b_s, b_t, cidx);
    mega_kernel<<<MEGA_CTAS, MEGA_THR, MEGA_SMEM>>>(m1, m2, idx, out);
}

// round 13
// speedup vs baseline: 1.1017x; 1.0129x over previous
#include <cuda_runtime.h>
#include <cuda_bf16.h>
#include <cstdint>

#define BSZ    256
#define FEAT   128
#define KP1    4097
#define PAD    4100
#define NDATA  500000
#define SDIM   1024
#define TDIM   2048
#define MEMELEMS 64000000
#define TOTAL  (BSZ * KP1)        // 1,048,832
#define EPSF   1e-7f
#define MPN    (4096.0f / 500000.0f)
#define KSPLIT 8
#define FULLM  0xffffffffu
#define CAP    16
#define MEGA_CTAS 148
#define MEGA_THR  1024
#define NWARPS   (MEGA_CTAS * 32)  // 4736
#define CHUNK    106               // 4736*106 = 502,016 >= NDATA

__device__ float g_es[BSZ * FEAT];
__device__ float g_et[BSZ * FEAT];
__device__ float g_part_s[KSPLIT * BSZ * FEAT];
__device__ float g_part_t[KSPLIT * BSZ * FEAT];
__device__ float g_out_s[BSZ * PAD];
__device__ float g_out_t[BSZ * PAD];
__device__ float g_sums[3];          // zero-init; self-cleaned each replay
__device__ int   g_ticket;
__device__ int   g_rtcnt[128];       // zero-init; self-resetting
__device__ int   g_cnt[NDATA];       // zero-init; cleaned in mega P2
__device__ int   g_tasklist[NDATA * CAP];   // packed rec = (b<<13)|k
__device__ int   g_bar_cnt;          // zero-init; self-resetting
__device__ volatile int g_bar_gen;   // monotonic across replays

// ---------------------------------------------------------------- grid barrier (all 148 CTAs resident)
__device__ __forceinline__ void grid_sync() {
    __threadfence();
    __syncthreads();
    if (threadIdx.x == 0) {
        const int gen = g_bar_gen;
        if (atomicAdd(&g_bar_cnt, 1) == MEGA_CTAS - 1) {
            g_bar_cnt = 0;
            __threadfence();
            g_bar_gen = gen + 1;
        } else {
            while (g_bar_gen == gen) { }
        }
        __threadfence();
    }
    __syncthreads();
}

// ---------------------------------------------------------------- L1: embed partial + scatter + ticket-norm
__global__ __launch_bounds__(128) void embed_scatter(const float* __restrict__ f_s,
                                                     const float* __restrict__ f_t,
                                                     const float* __restrict__ W_s,
                                                     const float* __restrict__ W_t,
                                                     const float* __restrict__ b_s,
                                                     const float* __restrict__ b_t,
                                                     const int* __restrict__ cidx) {
    const int bid = blockIdx.x;
    const int t = threadIdx.x;
    if (bid >= 1024) {
        const int tid = (bid - 1024) * 128 + t;
        #pragma unroll 1
        for (int i = tid; i < TOTAL; i += 1024 * 128) {
            const int row = __ldg(cidx + i);
            const int b = i / KP1;
            const int k = i - b * KP1;
            const int pos = atomicAdd(&g_cnt[row], 1);
            if (pos < CAP)
                g_tasklist[(size_t)row * CAP + pos] = (b << 13) | k;
        }
        return;
    }
    __shared__ float fsh[4 * 256];
    __shared__ float sh[4];
    __shared__ int sh_last;
    const bool is_t = bid >= 512;
    const int id = is_t ? bid - 512 : bid;
    const int rt = id >> 3;
    const int ks = id & 7;
    const int Kd = is_t ? TDIM : SDIM;
    const int kchunk = Kd / KSPLIT;
    const int k0 = ks * kchunk;
    const float* f = is_t ? f_t : f_s;
    const float* W = is_t ? W_t : W_s;
    float* part = is_t ? g_part_t : g_part_s;
    const int rows0 = rt * 4;

    #pragma unroll
    for (int r = 0; r < 4; ++r)
        for (int k = t; k < kchunk; k += 128)
            fsh[r * 256 + k] = f[(rows0 + r) * Kd + k0 + k];
    __syncthreads();

    float a0 = 0.f, a1 = 0.f, a2 = 0.f, a3 = 0.f;
    const float* Wp = W + (size_t)k0 * FEAT + t;
    #pragma unroll 8
    for (int k = 0; k < kchunk; ++k) {
        float w = Wp[(size_t)k * FEAT];
        a0 += fsh[k] * w;
        a1 += fsh[256 + k] * w;
        a2 += fsh[512 + k] * w;
        a3 += fsh[768 + k] * w;
    }
    part[(ks * BSZ + rows0 + 0) * FEAT + t] = a0;
    part[(ks * BSZ + rows0 + 1) * FEAT + t] = a1;
    part[(ks * BSZ + rows0 + 2) * FEAT + t] = a2;
    part[(ks * BSZ + rows0 + 3) * FEAT + t] = a3;

    __threadfence();
    __syncthreads();
    const int tcx = (is_t ? 64 : 0) + rt;
    if (t == 0) sh_last = (atomicAdd(&g_rtcnt[tcx], 1) == KSPLIT - 1);
    __syncthreads();
    if (!sh_last) return;
    __threadfence();

    const float* bias = is_t ? b_t : b_s;
    float* out = is_t ? g_et : g_es;
    const int lane = t & 31, w_ = t >> 5;
    #pragma unroll
    for (int r = 0; r < 4; ++r) {
        float v = bias[t];
        #pragma unroll
        for (int kk = 0; kk < KSPLIT; ++kk)
            v += part[(kk * BSZ + rows0 + r) * FEAT + t];
        float sq = v * v;
        #pragma unroll
        for (int o = 16; o; o >>= 1) sq += __shfl_xor_sync(FULLM, sq, o);
        if (lane == 0) sh[w_] = sq;
        __syncthreads();
        float tot = sh[0] + sh[1] + sh[2] + sh[3];
        __syncthreads();
        out[(rows0 + r) * FEAT + t] = v / sqrtf(tot);
    }
    if (t == 0) g_rtcnt[tcx] = 0;
}

// ---------------------------------------------------------------- L2: MEGA
__global__ __launch_bounds__(MEGA_THR, 1) void mega_kernel(const float* __restrict__ m1,
                                                           const float* __restrict__ m2,
                                                           const int* __restrict__ idx,
                                                           float* __restrict__ out) {
    extern __shared__ char sm[];
    uint4* eint = (uint4*)sm;                 // 128 KB: {es bf16 x4, et bf16 x4} per (b,lane)
    __shared__ float shT[32], shS[32];

    const int t = threadIdx.x;
    for (int i = t; i < BSZ * 32; i += MEGA_THR) {
        const int b = i >> 5, l = i & 31;
        const float4 e1 = *((const float4*)(g_es + b * FEAT) + l);
        const float4 e2 = *((const float4*)(g_et + b * FEAT) + l);
        uint4 e;
        __nv_bfloat162 v;
        v = __floats2bfloat162_rn(e1.x, e1.y); e.x = *(unsigned*)&v;
        v = __floats2bfloat162_rn(e1.z, e1.w); e.y = *(unsigned*)&v;
        v = __floats2bfloat162_rn(e2.x, e2.y); e.z = *(unsigned*)&v;
        v = __floats2bfloat162_rn(e2.z, e2.w); e.w = *(unsigned*)&v;
        eint[i] = e;
    }
    __syncthreads();

    const int lane = t & 31;
    const int w = t >> 5;
    const int gw = blockIdx.x * 32 + w;
    const int r0 = gw * CHUNK;
    const int rend = min(r0 + CHUNK, NDATA);

    float sumT = 0.f, sumS = 0.f;

    // ======== Phase 1: single-pass row sweep, depth-2 prefetch ring ========
    if (r0 < rend) {
        float4* o1b = (float4*)out;
        float4* o2b = (float4*)(out + MEMELEMS);

        float carry1 = 0.f, carry2 = 0.f;
        if (r0 > 0 && lane == 0) {
            carry1 = __ldg(m1 + (size_t)r0 * FEAT - 1);
            carry2 = __ldg(m2 + (size_t)r0 * FEAT - 1);
        }

        float4 Ar[2], Cr[2];
        int cntr[2], recr[2];
        Ar[0] = __ldg((const float4*)m1 + (size_t)r0 * 32 + lane);
        Cr[0] = __ldg((const float4*)m2 + (size_t)r0 * 32 + lane);
        cntr[0] = __ldg(&g_cnt[r0]);
        recr[0] = (lane < CAP) ? __ldg(&g_tasklist[(size_t)r0 * CAP + lane]) : 0;
        if (r0 + 1 < rend) {
            Ar[1] = __ldg((const float4*)m1 + (size_t)(r0 + 1) * 32 + lane);
            Cr[1] = __ldg((const float4*)m2 + (size_t)(r0 + 1) * 32 + lane);
            cntr[1] = __ldg(&g_cnt[r0 + 1]);
            recr[1] = (lane < CAP) ? __ldg(&g_tasklist[(size_t)(r0 + 1) * CAP + lane]) : 0;
        } else { cntr[1] = 0; recr[1] = 0; }

        #pragma unroll 2
        for (int r = r0; r < rend; ++r) {
            const int p = (r - r0) & 1;
            const float4 A = Ar[p];
            const float4 C = Cr[p];
            const int cnt = cntr[p];
            const int rec = recr[p];

            // ---- NCE dots: pairs + dual-tree reduction (12 shfl/pair)
            const int c = min(cnt, CAP);
            #pragma unroll 1
            for (int tt = 0; tt < c; tt += 2) {
                const bool has2 = (tt + 1 < c);
                const int rA = __shfl_sync(FULLM, rec, tt);
                const int rB = __shfl_sync(FULLM, rec, has2 ? tt + 1 : tt);
                const int bA = rA >> 13, kA = rA & 8191;
                const int bB = rB >> 13, kB = rB & 8191;
                const uint4 eA = eint[(bA << 5) + lane];
                const uint4 eB = eint[(bB << 5) + lane];
                const float2 sA0 = __bfloat1622float2(*(const __nv_bfloat162*)&eA.x);
                const float2 sA1 = __bfloat1622float2(*(const __nv_bfloat162*)&eA.y);
                const float2 tA0 = __bfloat1622float2(*(const __nv_bfloat162*)&eA.z);
                const float2 tA1 = __bfloat1622float2(*(const __nv_bfloat162*)&eA.w);
                const float2 sB0 = __bfloat1622float2(*(const __nv_bfloat162*)&eB.x);
                const float2 sB1 = __bfloat1622float2(*(const __nv_bfloat162*)&eB.y);
                const float2 tB0 = __bfloat1622float2(*(const __nv_bfloat162*)&eB.z);
                const float2 tB1 = __bfloat1622float2(*(const __nv_bfloat162*)&eB.w);
                float dtA = A.x * tA0.x + A.y * tA0.y + A.z * tA1.x + A.w * tA1.y;
                float dsA = C.x * sA0.x + C.y * sA0.y + C.z * sA1.x + C.w * sA1.y;
                float dtB = A.x * tB0.x + A.y * tB0.y + A.z * tB1.x + A.w * tB1.y;
                float dsB = C.x * sB0.x + C.y * sB0.y + C.z * sB1.x + C.w * sB1.y;
                // half-reduce both, then fold ds into upper half lanes
                dtA += __shfl_xor_sync(FULLM, dtA, 16);
                dsA += __shfl_xor_sync(FULLM, dsA, 16);
                dtB += __shfl_xor_sync(FULLM, dtB, 16);
                dsB += __shfl_xor_sync(FULLM, dsB, 16);
                float vA = (lane & 16) ? dsA : dtA;
                float vB = (lane & 16) ? dsB : dtB;
                #pragma unroll
                for (int o = 8; o; o >>= 1) {
                    vA += __shfl_xor_sync(FULLM, vA, o);
                    vB += __shfl_xor_sync(FULLM, vB, o);
                }
                // lane0: dt totals; lane16: ds totals
                if (lane == 0) {
                    const float otA = __expf(vA * (1.0f / 0.07f));
                    g_out_t[bA * PAD + kA] = otA;
                    sumT += otA;
                    if (has2) {
                        const float otB = __expf(vB * (1.0f / 0.07f));
                        g_out_t[bB * PAD + kB] = otB;
                        sumT += otB;
                    }
                } else if (lane == 16) {
                    const float osA = __expf(vA * (1.0f / 0.07f));
                    g_out_s[bA * PAD + kA] = osA;
                    sumS += osA;
                    if (has2) {
                        const float osB = __expf(vB * (1.0f / 0.07f));
                        g_out_s[bB * PAD + kB] = osB;
                        sumS += osB;
                    }
                }
            }

            // ---- copy-out (shifted +1): aligned float4 stores via shfl carry
            float p1 = __shfl_up_sync(FULLM, A.w, 1);
            float p2 = __shfl_up_sync(FULLM, C.w, 1);
            if (lane == 0) { p1 = carry1; p2 = carry2; }
            const int ci = r * 32 + lane;
            if (r == 0 && lane == 0) {
                out[1] = A.x; out[2] = A.y; out[3] = A.z;
                out[MEMELEMS + 1] = C.x; out[MEMELEMS + 2] = C.y; out[MEMELEMS + 3] = C.z;
            } else {
                o1b[ci] = make_float4(p1, A.x, A.y, A.z);
                o2b[ci] = make_float4(p2, C.x, C.y, C.z);
            }
            if (r == NDATA - 1 && lane == 31) {
                out[MEMELEMS] = A.w;
                out[(size_t)2 * MEMELEMS] = C.w;
            }
            carry1 = __shfl_sync(FULLM, A.w, 31);
            carry2 = __shfl_sync(FULLM, C.w, 31);

            // ---- prefetch row r+2 into the slot just consumed
            if (r + 2 < rend) {
                Ar[p] = __ldg((const float4*)m1 + (size_t)(r + 2) * 32 + lane);
                Cr[p] = __ldg((const float4*)m2 + (size_t)(r + 2) * 32 + lane);
                cntr[p] = __ldg(&g_cnt[r + 2]);
                recr[p] = (lane < CAP) ? __ldg(&g_tasklist[(size_t)(r + 2) * CAP + lane]) : 0;
            }
        }
    }

    if (lane == 0)  shT[w] = sumT;
    if (lane == 16) shS[w] = sumS;
    __syncthreads();
    if (t == 0) {
        float aT = 0.f, aS = 0.f;
        #pragma unroll
        for (int i = 0; i < 32; ++i) { aT += shT[i]; aS += shS[i]; }
        atomicAdd(&g_sums[0], aT);
        atomicAdd(&g_sums[1], aS);
    }

    // ======== barrier ========
    grid_sync();

    // ======== Phase 2: loss + update + cleanup ========
    const int gt = blockIdx.x * MEGA_THR + t;
    const int T = MEGA_CTAS * MEGA_THR;

    if (gw < BSZ) {
        const int b = gw;
        const int row = __ldg(idx + b);
        float* o1 = out + 1;
        float* o2 = out + 1 + MEMELEMS;
        const float4 mv1 = __ldg((const float4*)m1 + (size_t)row * 32 + lane);
        const float4 mv2 = __ldg((const float4*)m2 + (size_t)row * 32 + lane);
        const float4 e1 = *((const float4*)(g_es + b * FEAT) + lane);
        const float4 e2 = *((const float4*)(g_et + b * FEAT) + lane);
        float v1[4] = {0.5f * (mv1.x + e1.x), 0.5f * (mv1.y + e1.y),
                       0.5f * (mv1.z + e1.z), 0.5f * (mv1.w + e1.w)};
        float v2[4] = {0.5f * (mv2.x + e2.x), 0.5f * (mv2.y + e2.y),
                       0.5f * (mv2.z + e2.z), 0.5f * (mv2.w + e2.w)};
        float s1 = v1[0]*v1[0] + v1[1]*v1[1] + v1[2]*v1[2] + v1[3]*v1[3];
        float s2 = v2[0]*v2[0] + v2[1]*v2[1] + v2[2]*v2[2] + v2[3]*v2[3];
        #pragma unroll
        for (int o = 16; o; o >>= 1) {
            s1 += __shfl_xor_sync(FULLM, s1, o);
            s2 += __shfl_xor_sync(FULLM, s2, o);
        }
        const float in1 = rsqrtf(s1), in2 = rsqrtf(s2);
        const size_t off = (size_t)row * FEAT + lane * 4;
        #pragma unroll
        for (int j = 0; j < 4; ++j) {
            o1[off + j] = v1[j] * in1;
            o2[off + j] = v2[j] * in2;
        }
    }

    {
        const float invZt = (float)TOTAL / ((float)NDATA * g_sums[0]);
        const float invZs = (float)TOTAL / ((float)NDATA * g_sums[1]);
        float acc = 0.f;
        #pragma unroll 1
        for (int it = gt; it < BSZ * 1025; it += T) {
            const int b = it / 1025;
            const int k = (it - b * 1025) * 4;
            float4 vs = *((const float4*)(g_out_s + b * PAD + k));
            float4 vt = *((const float4*)(g_out_t + b * PAD + k));
            float xs[4] = {vs.x, vs.y, vs.z, vs.w};
            float xt[4] = {vt.x, vt.y, vt.z, vt.w};
            #pragma unroll
            for (int c = 0; c < 4; ++c) {
                if (k + c < KP1) {
                    float xS = xs[c] * invZs;
                    float xT = xt[c] * invZt;
                    if (k + c == 0) {
                        acc += logf(xS / (xS + MPN + EPSF)) + logf(xT / (xT + MPN + EPSF));
                    } else {
                        acc -= logf(1.0f + (xS + EPSF) * (1.0f / MPN));
                        acc -= logf(1.0f + (xT + EPSF) * (1.0f / MPN));
                    }
                }
            }
        }
        #pragma unroll
        for (int o = 16; o; o >>= 1) acc += __shfl_xor_sync(FULLM, acc, o);
        if (lane == 0) shT[w] = acc;
    }

    #pragma unroll 1
    for (int z = gt; z < NDATA; z += T) g_cnt[z] = 0;

    __syncthreads();
    if (t == 0) {
        float tot = 0.f;
        #pragma unroll
        for (int i = 0; i < 32; ++i) tot += shT[i];
        atomicAdd(&g_sums[2], tot);
        __threadfence();
        const int tk = atomicAdd(&g_ticket, 1);
        if (tk == MEGA_CTAS - 1) {
            out[0] = -g_sums[2] / (float)BSZ;
            g_sums[0] = 0.f; g_sums[1] = 0.f; g_sums[2] = 0.f;
            g_ticket = 0;
        }
    }
}

// ---------------------------------------------------------------- launch
extern "C" void kernel_launch(void* const* d_in, const int* in_sizes, int n_in,
                              void* d_out, int out_size) {
    const float* f_s  = (const float*)d_in[0];
    const float* f_t  = (const float*)d_in[1];
    const int*   idx  = (const int*)  d_in[2];
    const int*   cidx = (const int*)  d_in[3];
    const float* W_s  = (const float*)d_in[4];
    const float* b_s  = (const float*)d_in[5];
    const float* W_t  = (const float*)d_in[6];
    const float* b_t  = (const float*)d_in[7];
    const float* m1   = (const float*)d_in[8];
    const float* m2   = (const float*)d_in[9];
    float* out = (float*)d_out;

    static int smem_set = 0;
    const int MEGA_SMEM = 131072;
    if (!smem_set) {
        cudaFuncSetAttribute(mega_kernel, cudaFuncAttributeMaxDynamicSharedMemorySize, MEGA_SMEM);
        smem_set = 1;
    }

    embed_scatter<<<2048, 128>>>(f_s, f_t, W_s, W_t, b_s, b_t, cidx);
    mega_kernel<<<MEGA_CTAS, MEGA_THR, MEGA_SMEM>>>(m1, m2, idx, out);
}